// round 12
// baseline (speedup 1.0000x reference)
#include <cuda_runtime.h>
#include <cuda_fp16.h>

#define S_LEN 128
#define NH 8
#define INF9 1.0e9f

// Weight fragments in fp16 B-frag layout (uint = half2), prepped per launch.
__device__ unsigned g_Wfu[3 * 8 * 1024];   // [z][h][kg4][nf4][lane32][p2]
__device__ unsigned g_Wofu[8 * 1024];      // [h][kg2][nf8][lane32][p2]
__device__ unsigned g_B16[262144];         // bias as half2 pairs (same order)

__device__ __forceinline__ unsigned pk(float a, float b) {
  __half2 h = __floats2half2_rn(a, b);
  return *(unsigned*)&h;
}
__device__ __forceinline__ float2 h22f2(unsigned u) {
  __half2 h = *(__half2*)&u;
  return __half22float2(h);
}

// D += A(16x16 f16) * B(16x8 f16), fp32 accum.
__device__ __forceinline__ void mma16(float4& c, unsigned a0, unsigned a1,
                                      unsigned a2, unsigned a3, unsigned b0,
                                      unsigned b1) {
  asm volatile(
      "mma.sync.aligned.m16n8k16.row.col.f32.f16.f16.f32 "
      "{%0,%1,%2,%3}, {%4,%5,%6,%7}, {%8,%9}, {%0,%1,%2,%3};"
      : "+f"(c.x), "+f"(c.y), "+f"(c.z), "+f"(c.w)
      : "r"(a0), "r"(a1), "r"(a2), "r"(a3), "r"(b0), "r"(b1));
}

// ---------------------------------------------------------------------------
// Prep: weights -> per-head fp16 B-frag layouts (wq pre-scaled), AND
// bias fp32 -> fp16 pairs.
// ---------------------------------------------------------------------------
__global__ void prep_kernel(const float* __restrict__ wq,
                            const float* __restrict__ wk,
                            const float* __restrict__ wv,
                            const float* __restrict__ wo,
                            const float* __restrict__ bias) {
  const float scale = 0.17677669529663687f;  // 1/sqrt(32)
  int id = blockIdx.x * 256 + threadIdx.x;
  if (id < 24576) {
    int p = id & 1, lane = (id >> 1) & 31, nf = (id >> 6) & 3,
        kg = (id >> 8) & 3, h = (id >> 10) & 7, z = id >> 13;
    int r4 = lane >> 2, c4 = lane & 3;
    const float* w = (z == 0) ? wq : (z == 1) ? wk : wv;
    int k0 = kg * 16 + 2 * c4 + 8 * p;
    int col = h * 32 + nf * 8 + r4;
    float v0 = w[k0 * 256 + col], v1 = w[(k0 + 1) * 256 + col];
    if (z == 0) { v0 *= scale; v1 *= scale; }
    g_Wfu[id] = pk(v0, v1);
  } else if (id < 32768) {
    int id2 = id - 24576;
    int p = id2 & 1, lane = (id2 >> 1) & 31, nf = (id2 >> 6) & 7,
        kg = (id2 >> 9) & 1, h = id2 >> 10;
    int r4 = lane >> 2, c4 = lane & 3;
    int k0 = kg * 16 + 2 * c4 + 8 * p;
    int col = nf * 8 + r4;
    g_Wofu[id2] = pk(wo[(h * 32 + k0) * 64 + col],
                     wo[(h * 32 + k0 + 1) * 64 + col]);
  } else {
    int id2 = id - 32768;  // [0, 262144)
    float2 v = ((const float2*)bias)[id2];
    g_B16[id2] = pk(v.x, v.y);
  }
}

// ---------------------------------------------------------------------------
// Mega-fused kernel: one block per s, 256 threads (8 warps), warp owns 32
// rows (q and kv). fp16 operands, fp32 accum. Software-pipelined kt loop:
// S(kt+1) mma interleaves with exp(kt)/O-mma(kt); branch-free body.
// ---------------------------------------------------------------------------
#define XQ_OFF 0
#define XK_OFF 8192
#define WS_OFF 16384
#define KS_OFF 24576
#define VS_OFF 32768
#define MS_OFF 40960
#define FUSED_SMEM ((40960 + 256) * 4)
#define ONE2 0x3C003C00u

__global__ __launch_bounds__(256, 1) void fused_kernel(
    const float* __restrict__ xq, const float* __restrict__ xkv,
    const float* __restrict__ mask, const float* __restrict__ bo,
    float* __restrict__ outg) {
  extern __shared__ unsigned smu[];
  float* ms = (float*)(smu + MS_OFF);

  const int tid = threadIdx.x;
  const int s = blockIdx.x;

  // ---- stage Xq, Xkv as fp16 A-frags ----
  for (int i = tid; i < 4096; i += 256) {
    int row = i >> 4, k0 = (i & 15) * 4;
    float4 a = *(const float4*)(xq + (size_t)(s * 256 + row) * 64 + k0);
    float4 b = *(const float4*)(xkv + (size_t)(s * 256 + row) * 64 + k0);
    int rt = row >> 4, kg = k0 >> 4;
    int r4s = row & 7, eR = (row >> 3) & 1;
    int pi0 = (k0 & 15) >> 1;
    int c4a = pi0 & 3, hi = pi0 >> 2;
    int reg = eR + 2 * hi;
    int base = (((rt * 4 + kg) * 32 + r4s * 4 + c4a) * 4) + reg;
    smu[XQ_OFF + base] = pk(a.x, a.y);
    smu[XQ_OFF + base + 4] = pk(a.z, a.w);
    smu[XK_OFF + base] = pk(b.x, b.y);
    smu[XK_OFF + base + 4] = pk(b.z, b.w);
  }
  ms[tid] = (mask[s * 256 + tid] - 1.0f) * INF9 - 4.0f;  // -4: exp headroom

  const int w = tid >> 5, lane = tid & 31;
  const int r4 = lane >> 2, c4 = lane & 3;
  const int rt0 = w * 2;

  const uint4* Xq4 = (const uint4*)(smu + XQ_OFF);
  const uint4* Xk4 = (const uint4*)(smu + XK_OFF);

  // pre-stage W for head 0 into parity buffer 0
  {
    uint4* dst = (uint4*)(smu + WS_OFF);
#pragma unroll
    for (int j = 0; j < 4; j++) {
      dst[j * 256 + tid] = (j < 3) ? ((const uint4*)g_Wfu)[(j * 8) * 256 + tid]
                                   : ((const uint4*)g_Wofu)[tid];
    }
  }

  float4 oacc[2][8];
#pragma unroll
  for (int i = 0; i < 2; i++)
#pragma unroll
    for (int j = 0; j < 8; j++) oacc[i][j] = make_float4(0.f, 0.f, 0.f, 0.f);

#pragma unroll 1
  for (int h = 0; h < NH; h++) {
    const int p = h & 1;
    const uint2* Ws2 = (const uint2*)(smu + WS_OFF + p * 4096);
    const uint2* Ks2 = (const uint2*)(smu + KS_OFF + p * 4096);
    const uint2* Vs2 = (const uint2*)(smu + VS_OFF + p * 4096);

    __syncthreads();  // W[p] visible; Ks/Vs[p] safe to overwrite

    // ---- Q = Xq @ Wq_h -> qa A-frags ----
    uint4 qa[2][2];
    {
      float4 acc[2][4];
#pragma unroll
      for (int i = 0; i < 2; i++)
#pragma unroll
        for (int j = 0; j < 4; j++) acc[i][j] = make_float4(0.f, 0.f, 0.f, 0.f);
#pragma unroll
      for (int kg = 0; kg < 4; kg++) {
        uint4 A0 = Xq4[(rt0 * 4 + kg) * 32 + lane];
        uint4 A1 = Xq4[((rt0 + 1) * 4 + kg) * 32 + lane];
#pragma unroll
        for (int nf = 0; nf < 4; nf++) {
          uint2 B = Ws2[(kg * 4 + nf) * 32 + lane];
          mma16(acc[0][nf], A0.x, A0.y, A0.z, A0.w, B.x, B.y);
          mma16(acc[1][nf], A1.x, A1.y, A1.z, A1.w, B.x, B.y);
        }
      }
#pragma unroll
      for (int mt = 0; mt < 2; mt++)
#pragma unroll
        for (int kg = 0; kg < 2; kg++)
          qa[mt][kg] = make_uint4(pk(acc[mt][2 * kg].x, acc[mt][2 * kg].y),
                                  pk(acc[mt][2 * kg].z, acc[mt][2 * kg].w),
                                  pk(acc[mt][2 * kg + 1].x, acc[mt][2 * kg + 1].y),
                                  pk(acc[mt][2 * kg + 1].z, acc[mt][2 * kg + 1].w));
    }

    // ---- K = Xkv @ Wk_h -> Ks[p] scatter ----
    {
      float4 acc[2][4];
#pragma unroll
      for (int i = 0; i < 2; i++)
#pragma unroll
        for (int j = 0; j < 4; j++) acc[i][j] = make_float4(0.f, 0.f, 0.f, 0.f);
#pragma unroll
      for (int kg = 0; kg < 4; kg++) {
        uint4 A0 = Xk4[(rt0 * 4 + kg) * 32 + lane];
        uint4 A1 = Xk4[((rt0 + 1) * 4 + kg) * 32 + lane];
#pragma unroll
        for (int nf = 0; nf < 4; nf++) {
          uint2 B = Ws2[512 + (kg * 4 + nf) * 32 + lane];
          mma16(acc[0][nf], A0.x, A0.y, A0.z, A0.w, B.x, B.y);
          mma16(acc[1][nf], A1.x, A1.y, A1.z, A1.w, B.x, B.y);
        }
      }
#pragma unroll
      for (int mt = 0; mt < 2; mt++) {
        int kt = w * 2 + mt;
#pragma unroll
        for (int nf = 0; nf < 4; nf++) {
          int kgd = nf >> 1, pp = nf & 1;
          smu[KS_OFF + p * 4096 + (((kt * 2 + kgd) * 2 + 0) * 32 + lane) * 2 + pp] =
              pk(acc[mt][nf].x, acc[mt][nf].y);
          smu[KS_OFF + p * 4096 + (((kt * 2 + kgd) * 2 + 1) * 32 + lane) * 2 + pp] =
              pk(acc[mt][nf].z, acc[mt][nf].w);
        }
      }
    }

    // ---- V = Xkv @ Wv_h -> Vs[p] scatter ----
    {
      float4 acc[2][4];
#pragma unroll
      for (int i = 0; i < 2; i++)
#pragma unroll
        for (int j = 0; j < 4; j++) acc[i][j] = make_float4(0.f, 0.f, 0.f, 0.f);
#pragma unroll
      for (int kg = 0; kg < 4; kg++) {
        uint4 A0 = Xk4[(rt0 * 4 + kg) * 32 + lane];
        uint4 A1 = Xk4[((rt0 + 1) * 4 + kg) * 32 + lane];
#pragma unroll
        for (int nf = 0; nf < 4; nf++) {
          uint2 B = Ws2[1024 + (kg * 4 + nf) * 32 + lane];
          mma16(acc[0][nf], A0.x, A0.y, A0.z, A0.w, B.x, B.y);
          mma16(acc[1][nf], A1.x, A1.y, A1.z, A1.w, B.x, B.y);
        }
      }
      __half* Vh = (__half*)(smu + VS_OFF + p * 4096);
      int e = r4 & 1, cp = r4 >> 1;
#pragma unroll
      for (int mt = 0; mt < 2; mt++) {
        int kt = w * 2 + mt;
#pragma unroll
        for (int nf = 0; nf < 4; nf++) {
          int b0 = (((kt * 4 + nf) * 32 + (2 * c4) * 4 + cp) * 4) + e;
          int b1 = b0 + 16;
          Vh[b0] = __float2half_rn(acc[mt][nf].x);
          Vh[b0 + 2] = __float2half_rn(acc[mt][nf].z);
          Vh[b1] = __float2half_rn(acc[mt][nf].y);
          Vh[b1 + 2] = __float2half_rn(acc[mt][nf].w);
        }
      }
    }
    __syncthreads();  // Ks/Vs[p] ready

    // ---- prefetch next head's W into regs (overlaps with attention) ----
    uint4 wreg[4];
    if (h < NH - 1) {
#pragma unroll
      for (int j = 0; j < 4; j++)
        wreg[j] = (j < 3)
                      ? ((const uint4*)g_Wfu)[(j * 8 + h + 1) * 256 + tid]
                      : ((const uint4*)g_Wofu)[(h + 1) * 256 + tid];
    }

    // ---- attention (software-pipelined) ----
    float4 o[2][4];
#pragma unroll
    for (int mt = 0; mt < 2; mt++)
#pragma unroll
      for (int nf = 0; nf < 4; nf++) o[mt][nf] = make_float4(0.f, 0.f, 0.f, 0.f);
    float4 lpq[2] = {make_float4(0.f, 0.f, 0.f, 0.f),
                     make_float4(0.f, 0.f, 0.f, 0.f)};

    const unsigned* bb0[2]; const unsigned* bb1[2];
#pragma unroll
    for (int mt = 0; mt < 2; mt++) {
      bb0[mt] = g_B16 + h * 32768 + (w * 32 + mt * 16 + r4) * 128 + c4;
      bb1[mt] = bb0[mt] + 8 * 128;
    }
    unsigned cbuf[2][2][2][2];  // [slot][mt][nt][rowpair]
#pragma unroll
    for (int sl = 0; sl < 2; sl++)
#pragma unroll
      for (int mt = 0; mt < 2; mt++)
#pragma unroll
        for (int nt = 0; nt < 2; nt++) {
          cbuf[sl][mt][nt][0] = bb0[mt][sl * 8 + nt * 4];
          cbuf[sl][mt][nt][1] = bb1[mt][sl * 8 + nt * 4];
        }

    // prologue: compute S for kt=0 (consumes slot 0), then REFILL slot 0
    // with kt=2's bias (schedule fix: slot (kt+1)&1 must hold kt+1's bias
    // at the top of loop iteration kt).
    float4 Sf[2][2];
    {
      float2 m0 = *(const float2*)(ms + 2 * c4);
      float2 m1 = *(const float2*)(ms + 8 + 2 * c4);
#pragma unroll
      for (int mt = 0; mt < 2; mt++) {
        float2 c00 = h22f2(cbuf[0][mt][0][0]), c01 = h22f2(cbuf[0][mt][0][1]);
        float2 c10 = h22f2(cbuf[0][mt][1][0]), c11 = h22f2(cbuf[0][mt][1][1]);
        Sf[mt][0] = make_float4(c00.x + m0.x, c00.y + m0.y,
                                c01.x + m0.x, c01.y + m0.y);
        Sf[mt][1] = make_float4(c10.x + m1.x, c10.y + m1.y,
                                c11.x + m1.x, c11.y + m1.y);
      }
#pragma unroll
      for (int kg = 0; kg < 2; kg++) {
        uint2 Kb0 = Ks2[(kg * 2 + 0) * 32 + lane];
        uint2 Kb1 = Ks2[(kg * 2 + 1) * 32 + lane];
#pragma unroll
        for (int mt = 0; mt < 2; mt++) {
          mma16(Sf[mt][0], qa[mt][kg].x, qa[mt][kg].y, qa[mt][kg].z,
                qa[mt][kg].w, Kb0.x, Kb0.y);
          mma16(Sf[mt][1], qa[mt][kg].x, qa[mt][kg].y, qa[mt][kg].z,
                qa[mt][kg].w, Kb1.x, Kb1.y);
        }
      }
      // refill slot 0 with kt=2's bias
#pragma unroll
      for (int mt = 0; mt < 2; mt++)
#pragma unroll
        for (int nt = 0; nt < 2; nt++) {
          cbuf[0][mt][nt][0] = bb0[mt][2 * 8 + nt * 4];
          cbuf[0][mt][nt][1] = bb1[mt][2 * 8 + nt * 4];
        }
    }

#pragma unroll 1
    for (int kt = 0; kt < 15; kt++) {
      // V fragments for current chunk
      uint2 Vb[4];
#pragma unroll
      for (int nf = 0; nf < 4; nf++) Vb[nf] = Vs2[(kt * 4 + nf) * 32 + lane];
      // K fragments for next chunk
      uint2 Kb0[2], Kb1[2];
#pragma unroll
      for (int kg = 0; kg < 2; kg++) {
        Kb0[kg] = Ks2[(((kt + 1) * 2 + kg) * 2 + 0) * 32 + lane];
        Kb1[kg] = Ks2[(((kt + 1) * 2 + kg) * 2 + 1) * 32 + lane];
      }

      // exp of current S (MUFU stream)
      float pe[2][8];
#pragma unroll
      for (int mt = 0; mt < 2; mt++) {
        pe[mt][0] = __expf(Sf[mt][0].x); pe[mt][1] = __expf(Sf[mt][0].y);
        pe[mt][2] = __expf(Sf[mt][0].z); pe[mt][3] = __expf(Sf[mt][0].w);
        pe[mt][4] = __expf(Sf[mt][1].x); pe[mt][5] = __expf(Sf[mt][1].y);
        pe[mt][6] = __expf(Sf[mt][1].z); pe[mt][7] = __expf(Sf[mt][1].w);
      }

      // next S (HMMA stream, independent of exp)
      float4 Sn[2][2];
      {
        const int sl = (kt + 1) & 1;
        float2 m0 = *(const float2*)(ms + (kt + 1) * 16 + 2 * c4);
        float2 m1 = *(const float2*)(ms + (kt + 1) * 16 + 8 + 2 * c4);
#pragma unroll
        for (int mt = 0; mt < 2; mt++) {
          float2 c00 = h22f2(cbuf[sl][mt][0][0]), c01 = h22f2(cbuf[sl][mt][0][1]);
          float2 c10 = h22f2(cbuf[sl][mt][1][0]), c11 = h22f2(cbuf[sl][mt][1][1]);
          Sn[mt][0] = make_float4(c00.x + m0.x, c00.y + m0.y,
                                  c01.x + m0.x, c01.y + m0.y);
          Sn[mt][1] = make_float4(c10.x + m1.x, c10.y + m1.y,
                                  c11.x + m1.x, c11.y + m1.y);
        }
#pragma unroll
        for (int kg = 0; kg < 2; kg++) {
#pragma unroll
          for (int mt = 0; mt < 2; mt++) {
            mma16(Sn[mt][0], qa[mt][kg].x, qa[mt][kg].y, qa[mt][kg].z,
                  qa[mt][kg].w, Kb0[kg].x, Kb0[kg].y);
            mma16(Sn[mt][1], qa[mt][kg].x, qa[mt][kg].y, qa[mt][kg].z,
                  qa[mt][kg].w, Kb1[kg].x, Kb1[kg].y);
          }
        }
        // bias prefetch for kt+3 (clamped, branch-free) into consumed slot
        const int kn = (kt + 3 <= 15) ? (kt + 3) : 15;
#pragma unroll
        for (int mt = 0; mt < 2; mt++)
#pragma unroll
          for (int nt = 0; nt < 2; nt++) {
            cbuf[sl][mt][nt][0] = bb0[mt][kn * 8 + nt * 4];
            cbuf[sl][mt][nt][1] = bb1[mt][kn * 8 + nt * 4];
          }
      }

      // pack P, lp-mma, O-mma (depends on exp + Vb)
#pragma unroll
      for (int mt = 0; mt < 2; mt++) {
        unsigned pa0 = pk(pe[mt][0], pe[mt][1]), pa1 = pk(pe[mt][2], pe[mt][3]);
        unsigned pa2 = pk(pe[mt][4], pe[mt][5]), pa3 = pk(pe[mt][6], pe[mt][7]);
        mma16(lpq[mt], pa0, pa1, pa2, pa3, ONE2, ONE2);
#pragma unroll
        for (int nf = 0; nf < 4; nf++)
          mma16(o[mt][nf], pa0, pa1, pa2, pa3, Vb[nf].x, Vb[nf].y);
      }

#pragma unroll
      for (int mt = 0; mt < 2; mt++) { Sf[mt][0] = Sn[mt][0]; Sf[mt][1] = Sn[mt][1]; }
    }

    // epilogue: kt = 15
    {
      uint2 Vb[4];
#pragma unroll
      for (int nf = 0; nf < 4; nf++) Vb[nf] = Vs2[(15 * 4 + nf) * 32 + lane];
#pragma unroll
      for (int mt = 0; mt < 2; mt++) {
        unsigned pa0 = pk(__expf(Sf[mt][0].x), __expf(Sf[mt][0].y));
        unsigned pa1 = pk(__expf(Sf[mt][0].z), __expf(Sf[mt][0].w));
        unsigned pa2 = pk(__expf(Sf[mt][1].x), __expf(Sf[mt][1].y));
        unsigned pa3 = pk(__expf(Sf[mt][1].z), __expf(Sf[mt][1].w));
        mma16(lpq[mt], pa0, pa1, pa2, pa3, ONE2, ONE2);
#pragma unroll
        for (int nf = 0; nf < 4; nf++)
          mma16(o[mt][nf], pa0, pa1, pa2, pa3, Vb[nf].x, Vb[nf].y);
      }
    }

    // ---- normalize O, pack to A-frags, oacc += O @ Wo_h ----
#pragma unroll
    for (int mt = 0; mt < 2; mt++) {
      float inv0 = 1.0f / lpq[mt].x;   // row r4 sum
      float inv8 = 1.0f / lpq[mt].z;   // row r4+8 sum
#pragma unroll
      for (int kg = 0; kg < 2; kg++) {
        unsigned oa0 = pk(o[mt][2 * kg].x * inv0, o[mt][2 * kg].y * inv0);
        unsigned oa1 = pk(o[mt][2 * kg].z * inv8, o[mt][2 * kg].w * inv8);
        unsigned oa2 = pk(o[mt][2 * kg + 1].x * inv0, o[mt][2 * kg + 1].y * inv0);
        unsigned oa3 = pk(o[mt][2 * kg + 1].z * inv8, o[mt][2 * kg + 1].w * inv8);
#pragma unroll
        for (int nf = 0; nf < 8; nf++) {
          uint2 B = Ws2[1536 + (kg * 8 + nf) * 32 + lane];
          mma16(oacc[mt][nf], oa0, oa1, oa2, oa3, B.x, B.y);
        }
      }
    }

    // ---- store prefetched next-head W into opposite parity buffer ----
    if (h < NH - 1) {
      uint4* dst = (uint4*)(smu + WS_OFF + (p ^ 1) * 4096);
#pragma unroll
      for (int j = 0; j < 4; j++) dst[j * 256 + tid] = wreg[j];
    }
  }

  // ---- epilogue: + bo, store ----
#pragma unroll
  for (int mt = 0; mt < 2; mt++) {
    int row = s * 256 + w * 32 + mt * 16 + r4;
#pragma unroll
    for (int nf = 0; nf < 8; nf++) {
      int col = nf * 8 + 2 * c4;
      float2 bb = *(const float2*)(bo + col);
      *(float2*)(outg + (size_t)row * 64 + col) =
          make_float2(oacc[mt][nf].x + bb.x, oacc[mt][nf].y + bb.y);
      *(float2*)(outg + (size_t)(row + 8) * 64 + col) =
          make_float2(oacc[mt][nf].z + bb.x, oacc[mt][nf].w + bb.y);
    }
  }
}

// ---------------------------------------------------------------------------
extern "C" void kernel_launch(void* const* d_in, const int* in_sizes, int n_in,
                              void* d_out, int out_size) {
  const float* input_q  = (const float*)d_in[0];
  const float* input_kv = (const float*)d_in[1];
  const float* mask     = (const float*)d_in[2];
  const float* bias     = (const float*)d_in[3];
  const float* wq       = (const float*)d_in[4];
  const float* wk       = (const float*)d_in[5];
  const float* wv       = (const float*)d_in[6];
  const float* wo       = (const float*)d_in[7];
  const float* bo       = (const float*)d_in[8];
  float* out = (float*)d_out;

  cudaFuncSetAttribute(fused_kernel, cudaFuncAttributeMaxDynamicSharedMemorySize,
                       FUSED_SMEM);

  prep_kernel<<<1152, 256>>>(wq, wk, wv, wo, bias);
  fused_kernel<<<S_LEN, 256, FUSED_SMEM>>>(input_q, input_kv, mask, bo, out);
}

// round 13
// speedup vs baseline: 1.2518x; 1.2518x over previous
#include <cuda_runtime.h>
#include <cuda_fp16.h>

#define S_LEN 128
#define NH 8
#define INF9 1.0e9f
#define LOG2E 1.4426950408889634f

// Weight fragments in fp16 B-frag layout (uint = half2), prepped per launch.
__device__ unsigned g_Wfu[3 * 8 * 1024];   // [z][h][kg4][nf4][lane32][p2]
__device__ unsigned g_Wofu[8 * 1024];      // [h][kg2][nf8][lane32][p2]
__device__ unsigned g_B16[262144];         // bias*log2e as half2 pairs

__device__ __forceinline__ unsigned pk(float a, float b) {
  __half2 h = __floats2half2_rn(a, b);
  return *(unsigned*)&h;
}
__device__ __forceinline__ float2 h22f2(unsigned u) {
  __half2 h = *(__half2*)&u;
  return __half22float2(h);
}

// D += A(16x16 f16) * B(16x8 f16), fp32 accum.
__device__ __forceinline__ void mma16(float4& c, unsigned a0, unsigned a1,
                                      unsigned a2, unsigned a3, unsigned b0,
                                      unsigned b1) {
  asm volatile(
      "mma.sync.aligned.m16n8k16.row.col.f32.f16.f16.f32 "
      "{%0,%1,%2,%3}, {%4,%5,%6,%7}, {%8,%9}, {%0,%1,%2,%3};"
      : "+f"(c.x), "+f"(c.y), "+f"(c.z), "+f"(c.w)
      : "r"(a0), "r"(a1), "r"(a2), "r"(a3), "r"(b0), "r"(b1));
}

// ---------------------------------------------------------------------------
// Prep: weights -> per-head fp16 B-frag layouts. wq carries 1/sqrt(32)*log2e
// (scores land in log2 domain -> exp2f in the kernel, no per-exp FMUL).
// bias also pre-scaled by log2e.
// ---------------------------------------------------------------------------
__global__ void prep_kernel(const float* __restrict__ wq,
                            const float* __restrict__ wk,
                            const float* __restrict__ wv,
                            const float* __restrict__ wo,
                            const float* __restrict__ bias) {
  const float scale = 0.17677669529663687f * LOG2E;  // 1/sqrt(32) * log2e
  int id = blockIdx.x * 256 + threadIdx.x;
  if (id < 24576) {
    int p = id & 1, lane = (id >> 1) & 31, nf = (id >> 6) & 3,
        kg = (id >> 8) & 3, h = (id >> 10) & 7, z = id >> 13;
    int r4 = lane >> 2, c4 = lane & 3;
    const float* w = (z == 0) ? wq : (z == 1) ? wk : wv;
    int k0 = kg * 16 + 2 * c4 + 8 * p;
    int col = h * 32 + nf * 8 + r4;
    float v0 = w[k0 * 256 + col], v1 = w[(k0 + 1) * 256 + col];
    if (z == 0) { v0 *= scale; v1 *= scale; }
    g_Wfu[id] = pk(v0, v1);
  } else if (id < 32768) {
    int id2 = id - 24576;
    int p = id2 & 1, lane = (id2 >> 1) & 31, nf = (id2 >> 6) & 7,
        kg = (id2 >> 9) & 1, h = id2 >> 10;
    int r4 = lane >> 2, c4 = lane & 3;
    int k0 = kg * 16 + 2 * c4 + 8 * p;
    int col = nf * 8 + r4;
    g_Wofu[id2] = pk(wo[(h * 32 + k0) * 64 + col],
                     wo[(h * 32 + k0 + 1) * 64 + col]);
  } else {
    int id2 = id - 32768;  // [0, 262144)
    float2 v = ((const float2*)bias)[id2];
    g_B16[id2] = pk(v.x * LOG2E, v.y * LOG2E);
  }
}

// ---------------------------------------------------------------------------
// Mega-fused kernel (R10 structure): one block per s, 256 threads (8 warps),
// warp owns 32 rows (q and kv). fp16 operands, fp32 accum. Bias prefetch
// depth 2, next-head W prefetched into regs during attention, lp via
// ones-mma, exp2f (log2-domain scores).
// ---------------------------------------------------------------------------
#define XQ_OFF 0
#define XK_OFF 8192
#define WS_OFF 16384
#define KS_OFF 24576
#define VS_OFF 32768
#define MS_OFF 40960
#define FUSED_SMEM ((40960 + 256) * 4)
#define ONE2 0x3C003C00u

__global__ __launch_bounds__(256, 1) void fused_kernel(
    const float* __restrict__ xq, const float* __restrict__ xkv,
    const float* __restrict__ mask, const float* __restrict__ bo,
    float* __restrict__ outg) {
  extern __shared__ unsigned smu[];
  float* ms = (float*)(smu + MS_OFF);

  const int tid = threadIdx.x;
  const int s = blockIdx.x;

  // ---- stage Xq, Xkv as fp16 A-frags ----
  for (int i = tid; i < 4096; i += 256) {
    int row = i >> 4, k0 = (i & 15) * 4;
    float4 a = *(const float4*)(xq + (size_t)(s * 256 + row) * 64 + k0);
    float4 b = *(const float4*)(xkv + (size_t)(s * 256 + row) * 64 + k0);
    int rt = row >> 4, kg = k0 >> 4;
    int r4s = row & 7, eR = (row >> 3) & 1;
    int pi0 = (k0 & 15) >> 1;
    int c4a = pi0 & 3, hi = pi0 >> 2;
    int reg = eR + 2 * hi;
    int base = (((rt * 4 + kg) * 32 + r4s * 4 + c4a) * 4) + reg;
    smu[XQ_OFF + base] = pk(a.x, a.y);
    smu[XQ_OFF + base + 4] = pk(a.z, a.w);
    smu[XK_OFF + base] = pk(b.x, b.y);
    smu[XK_OFF + base + 4] = pk(b.z, b.w);
  }
  // mask and -4 headroom, pre-scaled by log2e (scores live in log2 domain)
  ms[tid] = ((mask[s * 256 + tid] - 1.0f) * INF9 - 4.0f) * LOG2E;

  const int w = tid >> 5, lane = tid & 31;
  const int r4 = lane >> 2, c4 = lane & 3;
  const int rt0 = w * 2;

  const uint4* Xq4 = (const uint4*)(smu + XQ_OFF);
  const uint4* Xk4 = (const uint4*)(smu + XK_OFF);

  // pre-stage W for head 0 into parity buffer 0
  {
    uint4* dst = (uint4*)(smu + WS_OFF);
#pragma unroll
    for (int j = 0; j < 4; j++) {
      dst[j * 256 + tid] = (j < 3) ? ((const uint4*)g_Wfu)[(j * 8) * 256 + tid]
                                   : ((const uint4*)g_Wofu)[tid];
    }
  }

  float4 oacc[2][8];
#pragma unroll
  for (int i = 0; i < 2; i++)
#pragma unroll
    for (int j = 0; j < 8; j++) oacc[i][j] = make_float4(0.f, 0.f, 0.f, 0.f);

#pragma unroll 1
  for (int h = 0; h < NH; h++) {
    const int p = h & 1;
    const uint2* Ws2 = (const uint2*)(smu + WS_OFF + p * 4096);
    const uint2* Ks2 = (const uint2*)(smu + KS_OFF + p * 4096);
    const uint2* Vs2 = (const uint2*)(smu + VS_OFF + p * 4096);

    __syncthreads();  // W[p] visible; Ks/Vs[p] safe to overwrite

    // ---- Q = Xq @ Wq_h -> qa A-frags ----
    uint4 qa[2][2];
    {
      float4 acc[2][4];
#pragma unroll
      for (int i = 0; i < 2; i++)
#pragma unroll
        for (int j = 0; j < 4; j++) acc[i][j] = make_float4(0.f, 0.f, 0.f, 0.f);
#pragma unroll
      for (int kg = 0; kg < 4; kg++) {
        uint4 A0 = Xq4[(rt0 * 4 + kg) * 32 + lane];
        uint4 A1 = Xq4[((rt0 + 1) * 4 + kg) * 32 + lane];
#pragma unroll
        for (int nf = 0; nf < 4; nf++) {
          uint2 B = Ws2[(kg * 4 + nf) * 32 + lane];
          mma16(acc[0][nf], A0.x, A0.y, A0.z, A0.w, B.x, B.y);
          mma16(acc[1][nf], A1.x, A1.y, A1.z, A1.w, B.x, B.y);
        }
      }
#pragma unroll
      for (int mt = 0; mt < 2; mt++)
#pragma unroll
        for (int kg = 0; kg < 2; kg++)
          qa[mt][kg] = make_uint4(pk(acc[mt][2 * kg].x, acc[mt][2 * kg].y),
                                  pk(acc[mt][2 * kg].z, acc[mt][2 * kg].w),
                                  pk(acc[mt][2 * kg + 1].x, acc[mt][2 * kg + 1].y),
                                  pk(acc[mt][2 * kg + 1].z, acc[mt][2 * kg + 1].w));
    }

    // ---- K = Xkv @ Wk_h -> Ks[p] scatter ----
    {
      float4 acc[2][4];
#pragma unroll
      for (int i = 0; i < 2; i++)
#pragma unroll
        for (int j = 0; j < 4; j++) acc[i][j] = make_float4(0.f, 0.f, 0.f, 0.f);
#pragma unroll
      for (int kg = 0; kg < 4; kg++) {
        uint4 A0 = Xk4[(rt0 * 4 + kg) * 32 + lane];
        uint4 A1 = Xk4[((rt0 + 1) * 4 + kg) * 32 + lane];
#pragma unroll
        for (int nf = 0; nf < 4; nf++) {
          uint2 B = Ws2[512 + (kg * 4 + nf) * 32 + lane];
          mma16(acc[0][nf], A0.x, A0.y, A0.z, A0.w, B.x, B.y);
          mma16(acc[1][nf], A1.x, A1.y, A1.z, A1.w, B.x, B.y);
        }
      }
#pragma unroll
      for (int mt = 0; mt < 2; mt++) {
        int kt = w * 2 + mt;
#pragma unroll
        for (int nf = 0; nf < 4; nf++) {
          int kgd = nf >> 1, pp = nf & 1;
          smu[KS_OFF + p * 4096 + (((kt * 2 + kgd) * 2 + 0) * 32 + lane) * 2 + pp] =
              pk(acc[mt][nf].x, acc[mt][nf].y);
          smu[KS_OFF + p * 4096 + (((kt * 2 + kgd) * 2 + 1) * 32 + lane) * 2 + pp] =
              pk(acc[mt][nf].z, acc[mt][nf].w);
        }
      }
    }

    // ---- V = Xkv @ Wv_h -> Vs[p] scatter ----
    {
      float4 acc[2][4];
#pragma unroll
      for (int i = 0; i < 2; i++)
#pragma unroll
        for (int j = 0; j < 4; j++) acc[i][j] = make_float4(0.f, 0.f, 0.f, 0.f);
#pragma unroll
      for (int kg = 0; kg < 4; kg++) {
        uint4 A0 = Xk4[(rt0 * 4 + kg) * 32 + lane];
        uint4 A1 = Xk4[((rt0 + 1) * 4 + kg) * 32 + lane];
#pragma unroll
        for (int nf = 0; nf < 4; nf++) {
          uint2 B = Ws2[1024 + (kg * 4 + nf) * 32 + lane];
          mma16(acc[0][nf], A0.x, A0.y, A0.z, A0.w, B.x, B.y);
          mma16(acc[1][nf], A1.x, A1.y, A1.z, A1.w, B.x, B.y);
        }
      }
      __half* Vh = (__half*)(smu + VS_OFF + p * 4096);
      int e = r4 & 1, cp = r4 >> 1;
#pragma unroll
      for (int mt = 0; mt < 2; mt++) {
        int kt = w * 2 + mt;
#pragma unroll
        for (int nf = 0; nf < 4; nf++) {
          int b0 = (((kt * 4 + nf) * 32 + (2 * c4) * 4 + cp) * 4) + e;
          int b1 = b0 + 16;
          Vh[b0] = __float2half_rn(acc[mt][nf].x);
          Vh[b0 + 2] = __float2half_rn(acc[mt][nf].z);
          Vh[b1] = __float2half_rn(acc[mt][nf].y);
          Vh[b1 + 2] = __float2half_rn(acc[mt][nf].w);
        }
      }
    }
    __syncthreads();  // Ks/Vs[p] ready

    // ---- prefetch next head's W into regs (overlaps with attention) ----
    uint4 wreg[4];
    if (h < NH - 1) {
#pragma unroll
      for (int j = 0; j < 4; j++)
        wreg[j] = (j < 3)
                      ? ((const uint4*)g_Wfu)[(j * 8 + h + 1) * 256 + tid]
                      : ((const uint4*)g_Wofu)[(h + 1) * 256 + tid];
    }

    // ---- attention ----
    float4 o[2][4];
#pragma unroll
    for (int mt = 0; mt < 2; mt++)
#pragma unroll
      for (int nf = 0; nf < 4; nf++) o[mt][nf] = make_float4(0.f, 0.f, 0.f, 0.f);
    float4 lpq[2] = {make_float4(0.f, 0.f, 0.f, 0.f),
                     make_float4(0.f, 0.f, 0.f, 0.f)};

    const unsigned* bb0[2]; const unsigned* bb1[2];
#pragma unroll
    for (int mt = 0; mt < 2; mt++) {
      bb0[mt] = g_B16 + h * 32768 + (w * 32 + mt * 16 + r4) * 128 + c4;
      bb1[mt] = bb0[mt] + 8 * 128;
    }
    // bias slots for kt and kt+1 (prefetch distance 2)
    unsigned cbuf[2][2][2][2];  // [slot][mt][nt][rowpair]
#pragma unroll
    for (int sl = 0; sl < 2; sl++)
#pragma unroll
      for (int mt = 0; mt < 2; mt++)
#pragma unroll
        for (int nt = 0; nt < 2; nt++) {
          cbuf[sl][mt][nt][0] = bb0[mt][sl * 8 + nt * 4];
          cbuf[sl][mt][nt][1] = bb1[mt][sl * 8 + nt * 4];
        }

#pragma unroll 2
    for (int kt = 0; kt < 16; kt++) {
      const int kv0 = kt * 16;
      const int sl = kt & 1;

      float2 m0 = *(const float2*)(ms + kv0 + 2 * c4);
      float2 m1 = *(const float2*)(ms + kv0 + 8 + 2 * c4);

      float4 Sf[2][2];
#pragma unroll
      for (int mt = 0; mt < 2; mt++) {
        float2 c00 = h22f2(cbuf[sl][mt][0][0]), c01 = h22f2(cbuf[sl][mt][0][1]);
        float2 c10 = h22f2(cbuf[sl][mt][1][0]), c11 = h22f2(cbuf[sl][mt][1][1]);
        Sf[mt][0] = make_float4(c00.x + m0.x, c00.y + m0.y,
                                c01.x + m0.x, c01.y + m0.y);
        Sf[mt][1] = make_float4(c10.x + m1.x, c10.y + m1.y,
                                c11.x + m1.x, c11.y + m1.y);
      }

      // prefetch bias for kt+2 into the slot just consumed
      if (kt < 14) {
#pragma unroll
        for (int mt = 0; mt < 2; mt++)
#pragma unroll
          for (int nt = 0; nt < 2; nt++) {
            cbuf[sl][mt][nt][0] = bb0[mt][(kt + 2) * 8 + nt * 4];
            cbuf[sl][mt][nt][1] = bb1[mt][(kt + 2) * 8 + nt * 4];
          }
      }

#pragma unroll
      for (int kg = 0; kg < 2; kg++) {
        uint2 Kb0 = Ks2[((kt * 2 + kg) * 2 + 0) * 32 + lane];
        uint2 Kb1 = Ks2[((kt * 2 + kg) * 2 + 1) * 32 + lane];
#pragma unroll
        for (int mt = 0; mt < 2; mt++) {
          mma16(Sf[mt][0], qa[mt][kg].x, qa[mt][kg].y, qa[mt][kg].z,
                qa[mt][kg].w, Kb0.x, Kb0.y);
          mma16(Sf[mt][1], qa[mt][kg].x, qa[mt][kg].y, qa[mt][kg].z,
                qa[mt][kg].w, Kb1.x, Kb1.y);
        }
      }

      uint2 Vb[4];
#pragma unroll
      for (int nf = 0; nf < 4; nf++) Vb[nf] = Vs2[(kt * 4 + nf) * 32 + lane];

#pragma unroll
      for (int mt = 0; mt < 2; mt++) {
        // log2-domain scores: single MUFU each, no FMUL
        float p00 = exp2f(Sf[mt][0].x), p01 = exp2f(Sf[mt][0].y);
        float p02 = exp2f(Sf[mt][0].z), p03 = exp2f(Sf[mt][0].w);
        float p10 = exp2f(Sf[mt][1].x), p11 = exp2f(Sf[mt][1].y);
        float p12 = exp2f(Sf[mt][1].z), p13 = exp2f(Sf[mt][1].w);
        unsigned pa0 = pk(p00, p01), pa1 = pk(p02, p03);
        unsigned pa2 = pk(p10, p11), pa3 = pk(p12, p13);
        // lp via ones-mma: exact fp32 row-sums of the SAME fp16 P
        mma16(lpq[mt], pa0, pa1, pa2, pa3, ONE2, ONE2);
#pragma unroll
        for (int nf = 0; nf < 4; nf++)
          mma16(o[mt][nf], pa0, pa1, pa2, pa3, Vb[nf].x, Vb[nf].y);
      }
    }

    // ---- normalize O, pack to A-frags, oacc += O @ Wo_h ----
#pragma unroll
    for (int mt = 0; mt < 2; mt++) {
      float inv0 = 1.0f / lpq[mt].x;   // row r4 sum
      float inv8 = 1.0f / lpq[mt].z;   // row r4+8 sum
#pragma unroll
      for (int kg = 0; kg < 2; kg++) {
        unsigned oa0 = pk(o[mt][2 * kg].x * inv0, o[mt][2 * kg].y * inv0);
        unsigned oa1 = pk(o[mt][2 * kg].z * inv8, o[mt][2 * kg].w * inv8);
        unsigned oa2 = pk(o[mt][2 * kg + 1].x * inv0, o[mt][2 * kg + 1].y * inv0);
        unsigned oa3 = pk(o[mt][2 * kg + 1].z * inv8, o[mt][2 * kg + 1].w * inv8);
#pragma unroll
        for (int nf = 0; nf < 8; nf++) {
          uint2 B = Ws2[1536 + (kg * 8 + nf) * 32 + lane];
          mma16(oacc[mt][nf], oa0, oa1, oa2, oa3, B.x, B.y);
        }
      }
    }

    // ---- store prefetched next-head W into opposite parity buffer ----
    if (h < NH - 1) {
      uint4* dst = (uint4*)(smu + WS_OFF + (p ^ 1) * 4096);
#pragma unroll
      for (int j = 0; j < 4; j++) dst[j * 256 + tid] = wreg[j];
    }
  }

  // ---- epilogue: + bo, store ----
#pragma unroll
  for (int mt = 0; mt < 2; mt++) {
    int row = s * 256 + w * 32 + mt * 16 + r4;
#pragma unroll
    for (int nf = 0; nf < 8; nf++) {
      int col = nf * 8 + 2 * c4;
      float2 bb = *(const float2*)(bo + col);
      *(float2*)(outg + (size_t)row * 64 + col) =
          make_float2(oacc[mt][nf].x + bb.x, oacc[mt][nf].y + bb.y);
      *(float2*)(outg + (size_t)(row + 8) * 64 + col) =
          make_float2(oacc[mt][nf].z + bb.x, oacc[mt][nf].w + bb.y);
    }
  }
}

// ---------------------------------------------------------------------------
extern "C" void kernel_launch(void* const* d_in, const int* in_sizes, int n_in,
                              void* d_out, int out_size) {
  const float* input_q  = (const float*)d_in[0];
  const float* input_kv = (const float*)d_in[1];
  const float* mask     = (const float*)d_in[2];
  const float* bias     = (const float*)d_in[3];
  const float* wq       = (const float*)d_in[4];
  const float* wk       = (const float*)d_in[5];
  const float* wv       = (const float*)d_in[6];
  const float* wo       = (const float*)d_in[7];
  const float* bo       = (const float*)d_in[8];
  float* out = (float*)d_out;

  cudaFuncSetAttribute(fused_kernel, cudaFuncAttributeMaxDynamicSharedMemorySize,
                       FUSED_SMEM);

  prep_kernel<<<1152, 256>>>(wq, wk, wv, wo, bias);
  fused_kernel<<<S_LEN, 256, FUSED_SMEM>>>(input_q, input_kv, mask, bo, out);
}

// round 15
// speedup vs baseline: 1.3648x; 1.0903x over previous
#include <cuda_runtime.h>
#include <cuda_fp16.h>

#define S_LEN 128
#define NH 8
#define INF9 1.0e9f
#define LOG2E 1.4426950408889634f

// Weight fragments in fp16 B-frag layout (uint = half2), prepped per launch.
__device__ unsigned g_Wfu[3 * 8 * 1024];   // [z][h][kg4][nf4][lane32][p2]
__device__ unsigned g_Wofu[8 * 1024];      // flat [kgAbs16][nf8][lane32][p2]
__device__ unsigned g_B16[262144];         // bias*log2e as half2 pairs
// X in fp16 A-frag layout: [rtAbs 2048][kg4][lane32][reg4]
__device__ unsigned g_Xqf[2048 * 512];
__device__ unsigned g_Xkf[2048 * 512];
// Normalized attention output, fp16 A-frags: [rtAbs 2048][kgAbs16][lane32][reg4]
__device__ unsigned g_Of[2048 * 2048];

__device__ __forceinline__ unsigned pk(float a, float b) {
  __half2 h = __floats2half2_rn(a, b);
  return *(unsigned*)&h;
}
__device__ __forceinline__ float2 h22f2(unsigned u) {
  __half2 h = *(__half2*)&u;
  return __half22float2(h);
}

__device__ __forceinline__ void mma16(float4& c, unsigned a0, unsigned a1,
                                      unsigned a2, unsigned a3, unsigned b0,
                                      unsigned b1) {
  asm volatile(
      "mma.sync.aligned.m16n8k16.row.col.f32.f16.f16.f32 "
      "{%0,%1,%2,%3}, {%4,%5,%6,%7}, {%8,%9}, {%0,%1,%2,%3};"
      : "+f"(c.x), "+f"(c.y), "+f"(c.z), "+f"(c.w)
      : "r"(a0), "r"(a1), "r"(a2), "r"(a3), "r"(b0), "r"(b1));
}

// ---------------------------------------------------------------------------
// Prep: weights -> fp16 B-frag layouts (wq pre-scaled by 1/sqrt(32)*log2e),
// bias -> fp16 * log2e.
// ---------------------------------------------------------------------------
__global__ void prep_kernel(const float* __restrict__ wq,
                            const float* __restrict__ wk,
                            const float* __restrict__ wv,
                            const float* __restrict__ wo,
                            const float* __restrict__ bias) {
  const float scale = 0.17677669529663687f * LOG2E;
  int id = blockIdx.x * 256 + threadIdx.x;
  if (id < 24576) {
    int p = id & 1, lane = (id >> 1) & 31, nf = (id >> 6) & 3,
        kg = (id >> 8) & 3, h = (id >> 10) & 7, z = id >> 13;
    int r4 = lane >> 2, c4 = lane & 3;
    const float* w = (z == 0) ? wq : (z == 1) ? wk : wv;
    int k0 = kg * 16 + 2 * c4 + 8 * p;
    int col = h * 32 + nf * 8 + r4;
    float v0 = w[k0 * 256 + col], v1 = w[(k0 + 1) * 256 + col];
    if (z == 0) { v0 *= scale; v1 *= scale; }
    g_Wfu[id] = pk(v0, v1);
  } else if (id < 32768) {
    int id2 = id - 24576;
    int p = id2 & 1, lane = (id2 >> 1) & 31, nf = (id2 >> 6) & 7,
        kg = (id2 >> 9) & 1, h = id2 >> 10;
    int r4 = lane >> 2, c4 = lane & 3;
    int k0 = kg * 16 + 2 * c4 + 8 * p;  // within head; global k = h*32 + k0
    int col = nf * 8 + r4;
    g_Wofu[id2] = pk(wo[(h * 32 + k0) * 64 + col],
                     wo[(h * 32 + k0 + 1) * 64 + col]);
  } else {
    int id2 = id - 32768;  // [0, 262144)
    float2 v = ((const float2*)bias)[id2];
    g_B16[id2] = pk(v.x * LOG2E, v.y * LOG2E);
  }
}

// ---------------------------------------------------------------------------
// Stage X (fp32 row-major) -> fp16 A-frag layout in global.
// ---------------------------------------------------------------------------
__global__ void stagex_kernel(const float* __restrict__ xq,
                              const float* __restrict__ xkv) {
  int id = blockIdx.x * 256 + threadIdx.x;  // 524288 total
  int row = id >> 4, k0 = (id & 15) * 4;
  float4 a = *(const float4*)(xq + (size_t)row * 64 + k0);
  float4 b = *(const float4*)(xkv + (size_t)row * 64 + k0);
  int rt = row >> 4, kg = k0 >> 4;
  int rr = row & 15, r4s = rr & 7, eR = rr >> 3;
  int pi0 = (k0 & 15) >> 1;
  int c4a = pi0 & 3, hi = pi0 >> 2;
  int reg = eR + 2 * hi;
  int base = (((rt * 4 + kg) * 32 + r4s * 4 + c4a) * 4) + reg;
  g_Xqf[base] = pk(a.x, a.y);
  g_Xqf[base + 4] = pk(a.z, a.w);
  g_Xkf[base] = pk(b.x, b.y);
  g_Xkf[base + 4] = pk(b.z, b.w);
}

// ---------------------------------------------------------------------------
// Attention kernel: grid (s, h) = 1024 blocks, 256 threads, 2 blocks/SM.
// Warp owns 32 q rows (mt=2) and 32 kv rows. Projects Q/K/V for its head,
// runs attention, writes normalized O as fp16 A-frags to g_Of.
// SMEM (uints): W[3072] Ks[4096] Vs[4096] ms[256f] = ~46 KB.
// ---------------------------------------------------------------------------
#define AWS_OFF 0
#define AKS_OFF 3072
#define AVS_OFF 7168
#define AMS_OFF 11264
#define ATTN_SMEM ((11264 + 256) * 4)
#define ONE2 0x3C003C00u

__global__ __launch_bounds__(256, 2) void attn_kernel(
    const float* __restrict__ mask) {
  extern __shared__ unsigned smu[];
  float* ms = (float*)(smu + AMS_OFF);

  const int tid = threadIdx.x;
  const int s = blockIdx.x, h = blockIdx.y;

  // stage this head's Wq/Wk/Wv frags (768 uint4)
  {
    uint4* dst = (uint4*)(smu + AWS_OFF);
#pragma unroll
    for (int i = tid; i < 768; i += 256) {
      int z = i >> 8, wi = i & 255;
      dst[i] = ((const uint4*)g_Wfu)[(z * 8 + h) * 256 + wi];
    }
  }
  ms[tid] = ((mask[s * 256 + tid] - 1.0f) * INF9 - 4.0f) * LOG2E;
  __syncthreads();

  const int w = tid >> 5, lane = tid & 31;
  const int r4 = lane >> 2, c4 = lane & 3;
  const int rtB = s * 16 + w * 2;  // this warp's abs row-tiles (q and kv)

  const uint2* Ws2 = (const uint2*)(smu + AWS_OFF);
  const uint2* Ks2 = (const uint2*)(smu + AKS_OFF);
  const uint2* Vs2 = (const uint2*)(smu + AVS_OFF);
  const uint4* Xqf4 = (const uint4*)g_Xqf;
  const uint4* Xkf4 = (const uint4*)g_Xkf;

  // ---- Q = Xq @ Wq_h -> qa A-frags ----
  uint4 qa[2][2];
  {
    float4 acc[2][4];
#pragma unroll
    for (int i = 0; i < 2; i++)
#pragma unroll
      for (int j = 0; j < 4; j++) acc[i][j] = make_float4(0.f, 0.f, 0.f, 0.f);
#pragma unroll
    for (int kg = 0; kg < 4; kg++) {
      uint4 A0 = Xqf4[((rtB + 0) * 4 + kg) * 32 + lane];
      uint4 A1 = Xqf4[((rtB + 1) * 4 + kg) * 32 + lane];
#pragma unroll
      for (int nf = 0; nf < 4; nf++) {
        uint2 B = Ws2[(kg * 4 + nf) * 32 + lane];
        mma16(acc[0][nf], A0.x, A0.y, A0.z, A0.w, B.x, B.y);
        mma16(acc[1][nf], A1.x, A1.y, A1.z, A1.w, B.x, B.y);
      }
    }
#pragma unroll
    for (int mt = 0; mt < 2; mt++)
#pragma unroll
      for (int kg = 0; kg < 2; kg++)
        qa[mt][kg] = make_uint4(pk(acc[mt][2 * kg].x, acc[mt][2 * kg].y),
                                pk(acc[mt][2 * kg].z, acc[mt][2 * kg].w),
                                pk(acc[mt][2 * kg + 1].x, acc[mt][2 * kg + 1].y),
                                pk(acc[mt][2 * kg + 1].z, acc[mt][2 * kg + 1].w));
  }

  // ---- K = Xkv @ Wk_h -> Ks scatter ----
  {
    float4 acc[2][4];
#pragma unroll
    for (int i = 0; i < 2; i++)
#pragma unroll
      for (int j = 0; j < 4; j++) acc[i][j] = make_float4(0.f, 0.f, 0.f, 0.f);
#pragma unroll
    for (int kg = 0; kg < 4; kg++) {
      uint4 A0 = Xkf4[((rtB + 0) * 4 + kg) * 32 + lane];
      uint4 A1 = Xkf4[((rtB + 1) * 4 + kg) * 32 + lane];
#pragma unroll
      for (int nf = 0; nf < 4; nf++) {
        uint2 B = Ws2[512 + (kg * 4 + nf) * 32 + lane];
        mma16(acc[0][nf], A0.x, A0.y, A0.z, A0.w, B.x, B.y);
        mma16(acc[1][nf], A1.x, A1.y, A1.z, A1.w, B.x, B.y);
      }
    }
#pragma unroll
    for (int mt = 0; mt < 2; mt++) {
      int kt = w * 2 + mt;  // local kv tile
#pragma unroll
      for (int nf = 0; nf < 4; nf++) {
        int kgd = nf >> 1, pp = nf & 1;
        smu[AKS_OFF + (((kt * 2 + kgd) * 2 + 0) * 32 + lane) * 2 + pp] =
            pk(acc[mt][nf].x, acc[mt][nf].y);
        smu[AKS_OFF + (((kt * 2 + kgd) * 2 + 1) * 32 + lane) * 2 + pp] =
            pk(acc[mt][nf].z, acc[mt][nf].w);
      }
    }
  }

  // ---- V = Xkv @ Wv_h -> Vs scatter ----
  {
    float4 acc[2][4];
#pragma unroll
    for (int i = 0; i < 2; i++)
#pragma unroll
      for (int j = 0; j < 4; j++) acc[i][j] = make_float4(0.f, 0.f, 0.f, 0.f);
#pragma unroll
    for (int kg = 0; kg < 4; kg++) {
      uint4 A0 = Xkf4[((rtB + 0) * 4 + kg) * 32 + lane];
      uint4 A1 = Xkf4[((rtB + 1) * 4 + kg) * 32 + lane];
#pragma unroll
      for (int nf = 0; nf < 4; nf++) {
        uint2 B = Ws2[1024 + (kg * 4 + nf) * 32 + lane];
        mma16(acc[0][nf], A0.x, A0.y, A0.z, A0.w, B.x, B.y);
        mma16(acc[1][nf], A1.x, A1.y, A1.z, A1.w, B.x, B.y);
      }
    }
    __half* Vh = (__half*)(smu + AVS_OFF);
    int e = r4 & 1, cp = r4 >> 1;
#pragma unroll
    for (int mt = 0; mt < 2; mt++) {
      int kt = w * 2 + mt;
#pragma unroll
      for (int nf = 0; nf < 4; nf++) {
        int b0 = (((kt * 4 + nf) * 32 + (2 * c4) * 4 + cp) * 4) + e;
        int b1 = b0 + 16;
        Vh[b0] = __float2half_rn(acc[mt][nf].x);
        Vh[b0 + 2] = __float2half_rn(acc[mt][nf].z);
        Vh[b1] = __float2half_rn(acc[mt][nf].y);
        Vh[b1 + 2] = __float2half_rn(acc[mt][nf].w);
      }
    }
  }
  __syncthreads();  // Ks/Vs ready

  // ---- attention ----
  float4 o[2][4];
#pragma unroll
  for (int mt = 0; mt < 2; mt++)
#pragma unroll
    for (int nf = 0; nf < 4; nf++) o[mt][nf] = make_float4(0.f, 0.f, 0.f, 0.f);
  float4 lpq[2] = {make_float4(0.f, 0.f, 0.f, 0.f),
                   make_float4(0.f, 0.f, 0.f, 0.f)};

  const unsigned* bb0[2]; const unsigned* bb1[2];
#pragma unroll
  for (int mt = 0; mt < 2; mt++) {
    bb0[mt] = g_B16 + h * 32768 + (w * 32 + mt * 16 + r4) * 128 + c4;
    bb1[mt] = bb0[mt] + 8 * 128;
  }
  unsigned cbuf[2][2][2][2];  // [slot][mt][nt][rowpair]
#pragma unroll
  for (int sl = 0; sl < 2; sl++)
#pragma unroll
    for (int mt = 0; mt < 2; mt++)
#pragma unroll
      for (int nt = 0; nt < 2; nt++) {
        cbuf[sl][mt][nt][0] = bb0[mt][sl * 8 + nt * 4];
        cbuf[sl][mt][nt][1] = bb1[mt][sl * 8 + nt * 4];
      }

#pragma unroll 2
  for (int kt = 0; kt < 16; kt++) {
    const int kv0 = kt * 16;
    const int sl = kt & 1;

    float2 m0 = *(const float2*)(ms + kv0 + 2 * c4);
    float2 m1 = *(const float2*)(ms + kv0 + 8 + 2 * c4);

    float4 Sf[2][2];
#pragma unroll
    for (int mt = 0; mt < 2; mt++) {
      float2 c00 = h22f2(cbuf[sl][mt][0][0]), c01 = h22f2(cbuf[sl][mt][0][1]);
      float2 c10 = h22f2(cbuf[sl][mt][1][0]), c11 = h22f2(cbuf[sl][mt][1][1]);
      Sf[mt][0] = make_float4(c00.x + m0.x, c00.y + m0.y,
                              c01.x + m0.x, c01.y + m0.y);
      Sf[mt][1] = make_float4(c10.x + m1.x, c10.y + m1.y,
                              c11.x + m1.x, c11.y + m1.y);
    }

    if (kt < 14) {
#pragma unroll
      for (int mt = 0; mt < 2; mt++)
#pragma unroll
        for (int nt = 0; nt < 2; nt++) {
          cbuf[sl][mt][nt][0] = bb0[mt][(kt + 2) * 8 + nt * 4];
          cbuf[sl][mt][nt][1] = bb1[mt][(kt + 2) * 8 + nt * 4];
        }
    }

#pragma unroll
    for (int kg = 0; kg < 2; kg++) {
      uint2 Kb0 = Ks2[((kt * 2 + kg) * 2 + 0) * 32 + lane];
      uint2 Kb1 = Ks2[((kt * 2 + kg) * 2 + 1) * 32 + lane];
#pragma unroll
      for (int mt = 0; mt < 2; mt++) {
        mma16(Sf[mt][0], qa[mt][kg].x, qa[mt][kg].y, qa[mt][kg].z,
              qa[mt][kg].w, Kb0.x, Kb0.y);
        mma16(Sf[mt][1], qa[mt][kg].x, qa[mt][kg].y, qa[mt][kg].z,
              qa[mt][kg].w, Kb1.x, Kb1.y);
      }
    }

    uint2 Vb[4];
#pragma unroll
    for (int nf = 0; nf < 4; nf++) Vb[nf] = Vs2[(kt * 4 + nf) * 32 + lane];

#pragma unroll
    for (int mt = 0; mt < 2; mt++) {
      float p00 = exp2f(Sf[mt][0].x), p01 = exp2f(Sf[mt][0].y);
      float p02 = exp2f(Sf[mt][0].z), p03 = exp2f(Sf[mt][0].w);
      float p10 = exp2f(Sf[mt][1].x), p11 = exp2f(Sf[mt][1].y);
      float p12 = exp2f(Sf[mt][1].z), p13 = exp2f(Sf[mt][1].w);
      unsigned pa0 = pk(p00, p01), pa1 = pk(p02, p03);
      unsigned pa2 = pk(p10, p11), pa3 = pk(p12, p13);
      mma16(lpq[mt], pa0, pa1, pa2, pa3, ONE2, ONE2);
#pragma unroll
      for (int nf = 0; nf < 4; nf++)
        mma16(o[mt][nf], pa0, pa1, pa2, pa3, Vb[nf].x, Vb[nf].y);
    }
  }

  // ---- normalize, pack to A-frags, write g_Of ----
  uint4* Of4 = (uint4*)g_Of;
#pragma unroll
  for (int mt = 0; mt < 2; mt++) {
    float inv0 = 1.0f / lpq[mt].x;
    float inv8 = 1.0f / lpq[mt].z;
    int rtA = rtB + mt;
#pragma unroll
    for (int kg = 0; kg < 2; kg++) {
      uint4 val = make_uint4(
          pk(o[mt][2 * kg].x * inv0, o[mt][2 * kg].y * inv0),
          pk(o[mt][2 * kg].z * inv8, o[mt][2 * kg].w * inv8),
          pk(o[mt][2 * kg + 1].x * inv0, o[mt][2 * kg + 1].y * inv0),
          pk(o[mt][2 * kg + 1].z * inv8, o[mt][2 * kg + 1].w * inv8));
      Of4[((size_t)rtA * 16 + h * 2 + kg) * 32 + lane] = val;
    }
  }
}

// ---------------------------------------------------------------------------
// Output projection: g_Of (fp16 A-frags) @ Wo + bo. Grid 128, 256 threads,
// warp = 32 rows (mt=2), K=256 (16 kg). Full Wo frags = 8192 uints = 32 KB.
// ---------------------------------------------------------------------------
#define OPROJ_SMEM (8192 * 4)

__global__ __launch_bounds__(256, 2) void oproj_kernel(
    const float* __restrict__ bo, float* __restrict__ outg) {
  extern __shared__ unsigned smo[];

  const int tid = threadIdx.x;
  {
    uint4* dst = (uint4*)smo;
#pragma unroll
    for (int i = tid; i < 2048; i += 256)
      dst[i] = ((const uint4*)g_Wofu)[i];
  }
  __syncthreads();

  const int w = tid >> 5, lane = tid & 31;
  const int r4 = lane >> 2, c4 = lane & 3;
  const int rt0 = blockIdx.x * 16 + w * 2;

  const uint2* Wo2 = (const uint2*)smo;
  const uint4* Of4 = (const uint4*)g_Of;

  float4 acc[2][8];
#pragma unroll
  for (int i = 0; i < 2; i++)
#pragma unroll
    for (int j = 0; j < 8; j++) acc[i][j] = make_float4(0.f, 0.f, 0.f, 0.f);

#pragma unroll 4
  for (int kg = 0; kg < 16; kg++) {
    uint4 A0 = Of4[((size_t)(rt0 + 0) * 16 + kg) * 32 + lane];
    uint4 A1 = Of4[((size_t)(rt0 + 1) * 16 + kg) * 32 + lane];
#pragma unroll
    for (int nf = 0; nf < 8; nf++) {
      uint2 B = Wo2[(kg * 8 + nf) * 32 + lane];
      mma16(acc[0][nf], A0.x, A0.y, A0.z, A0.w, B.x, B.y);
      mma16(acc[1][nf], A1.x, A1.y, A1.z, A1.w, B.x, B.y);
    }
  }

#pragma unroll
  for (int mt = 0; mt < 2; mt++) {
    int row = (rt0 + mt) * 16 + r4;
#pragma unroll
    for (int nf = 0; nf < 8; nf++) {
      int col = nf * 8 + 2 * c4;
      float2 bb = *(const float2*)(bo + col);
      *(float2*)(outg + (size_t)row * 64 + col) =
          make_float2(acc[mt][nf].x + bb.x, acc[mt][nf].y + bb.y);
      *(float2*)(outg + (size_t)(row + 8) * 64 + col) =
          make_float2(acc[mt][nf].z + bb.x, acc[mt][nf].w + bb.y);
    }
  }
}

// ---------------------------------------------------------------------------
extern "C" void kernel_launch(void* const* d_in, const int* in_sizes, int n_in,
                              void* d_out, int out_size) {
  const float* input_q  = (const float*)d_in[0];
  const float* input_kv = (const float*)d_in[1];
  const float* mask     = (const float*)d_in[2];
  const float* bias     = (const float*)d_in[3];
  const float* wq       = (const float*)d_in[4];
  const float* wk       = (const float*)d_in[5];
  const float* wv       = (const float*)d_in[6];
  const float* wo       = (const float*)d_in[7];
  const float* bo       = (const float*)d_in[8];
  float* out = (float*)d_out;

  cudaFuncSetAttribute(attn_kernel, cudaFuncAttributeMaxDynamicSharedMemorySize,
                       ATTN_SMEM);
  cudaFuncSetAttribute(oproj_kernel, cudaFuncAttributeMaxDynamicSharedMemorySize,
                       OPROJ_SMEM);

  prep_kernel<<<1152, 256>>>(wq, wk, wv, wo, bias);
  stagex_kernel<<<2048, 256>>>(input_q, input_kv);
  attn_kernel<<<dim3(S_LEN, NH), 256, ATTN_SMEM>>>(mask);
  oproj_kernel<<<128, 256, OPROJ_SMEM>>>(bo, out);
}

// round 16
// speedup vs baseline: 1.7300x; 1.2676x over previous
#include <cuda_runtime.h>
#include <cuda_fp16.h>

#define S_LEN 128
#define NH 8
#define INF9 1.0e9f
#define LOG2E 1.4426950408889634f

// Weight fragments in fp16 B-frag layout (uint = half2), prepped per launch.
__device__ unsigned g_Wfu[3 * 8 * 1024];   // [z][h][kg4][nf4][lane32][p2]
__device__ unsigned g_Wofu[8 * 1024];      // flat [kgAbs16][nf8][lane32][p2]
// bias*log2e in C-frag-major fp16: [h8][qt16][kt16][lane32][reg4 half2]
__device__ unsigned g_B16[262144];
// X in fp16 A-frag layout: [rtAbs 2048][kg4][lane32][reg4]
__device__ unsigned g_Xqf[2048 * 512];
__device__ unsigned g_Xkf[2048 * 512];
// Normalized attention output, fp16 A-frags: [rtAbs 2048][kgAbs16][lane32][reg4]
__device__ unsigned g_Of[2048 * 2048];

__device__ __forceinline__ unsigned pk(float a, float b) {
  __half2 h = __floats2half2_rn(a, b);
  return *(unsigned*)&h;
}
__device__ __forceinline__ float2 h22f2(unsigned u) {
  __half2 h = *(__half2*)&u;
  return __half22float2(h);
}

__device__ __forceinline__ void mma16(float4& c, unsigned a0, unsigned a1,
                                      unsigned a2, unsigned a3, unsigned b0,
                                      unsigned b1) {
  asm volatile(
      "mma.sync.aligned.m16n8k16.row.col.f32.f16.f16.f32 "
      "{%0,%1,%2,%3}, {%4,%5,%6,%7}, {%8,%9}, {%0,%1,%2,%3};"
      : "+f"(c.x), "+f"(c.y), "+f"(c.z), "+f"(c.w)
      : "r"(a0), "r"(a1), "r"(a2), "r"(a3), "r"(b0), "r"(b1));
}

// ---------------------------------------------------------------------------
// Prep: weights -> fp16 B-frag layouts (wq pre-scaled by 1/sqrt(32)*log2e);
// bias -> C-frag-major fp16 * log2e.
//   bias frag: reg = eR + 2*nt; value = {bias[row][col], bias[row][col+1]}
//   row = qt*16 + r4 + 8*eR, col = kt*16 + 2*c4 + 8*nt.
// ---------------------------------------------------------------------------
__global__ void prep_kernel(const float* __restrict__ wq,
                            const float* __restrict__ wk,
                            const float* __restrict__ wv,
                            const float* __restrict__ wo,
                            const float* __restrict__ bias) {
  const float scale = 0.17677669529663687f * LOG2E;
  int id = blockIdx.x * 256 + threadIdx.x;
  if (id < 24576) {
    int p = id & 1, lane = (id >> 1) & 31, nf = (id >> 6) & 3,
        kg = (id >> 8) & 3, h = (id >> 10) & 7, z = id >> 13;
    int r4 = lane >> 2, c4 = lane & 3;
    const float* w = (z == 0) ? wq : (z == 1) ? wk : wv;
    int k0 = kg * 16 + 2 * c4 + 8 * p;
    int col = h * 32 + nf * 8 + r4;
    float v0 = w[k0 * 256 + col], v1 = w[(k0 + 1) * 256 + col];
    if (z == 0) { v0 *= scale; v1 *= scale; }
    g_Wfu[id] = pk(v0, v1);
  } else if (id < 32768) {
    int id2 = id - 24576;
    int p = id2 & 1, lane = (id2 >> 1) & 31, nf = (id2 >> 6) & 7,
        kg = (id2 >> 9) & 1, h = id2 >> 10;
    int r4 = lane >> 2, c4 = lane & 3;
    int k0 = kg * 16 + 2 * c4 + 8 * p;  // within head; global k = h*32 + k0
    int col = nf * 8 + r4;
    g_Wofu[id2] = pk(wo[(h * 32 + k0) * 64 + col],
                     wo[(h * 32 + k0 + 1) * 64 + col]);
  } else {
    int id2 = id - 32768;  // [0, 262144) — one half2 of the bias frag layout
    int reg = id2 & 3, lane = (id2 >> 2) & 31, kt = (id2 >> 7) & 15,
        qt = (id2 >> 11) & 15, h = id2 >> 15;
    int r4 = lane >> 2, c4 = lane & 3;
    int row = qt * 16 + r4 + 8 * (reg & 1);
    int col = kt * 16 + 2 * c4 + 8 * (reg >> 1);
    const float* bp = bias + ((size_t)h * 256 + row) * 256 + col;
    g_B16[id2] = pk(bp[0] * LOG2E, bp[1] * LOG2E);
  }
}

// ---------------------------------------------------------------------------
// Stage X (fp32 row-major) -> fp16 A-frag layout in global.
// ---------------------------------------------------------------------------
__global__ void stagex_kernel(const float* __restrict__ xq,
                              const float* __restrict__ xkv) {
  int id = blockIdx.x * 256 + threadIdx.x;  // 524288 total
  int row = id >> 4, k0 = (id & 15) * 4;
  float4 a = *(const float4*)(xq + (size_t)row * 64 + k0);
  float4 b = *(const float4*)(xkv + (size_t)row * 64 + k0);
  int rt = row >> 4, kg = k0 >> 4;
  int rr = row & 15, r4s = rr & 7, eR = rr >> 3;
  int pi0 = (k0 & 15) >> 1;
  int c4a = pi0 & 3, hi = pi0 >> 2;
  int reg = eR + 2 * hi;
  int base = (((rt * 4 + kg) * 32 + r4s * 4 + c4a) * 4) + reg;
  g_Xqf[base] = pk(a.x, a.y);
  g_Xqf[base + 4] = pk(a.z, a.w);
  g_Xkf[base] = pk(b.x, b.y);
  g_Xkf[base + 4] = pk(b.z, b.w);
}

// ---------------------------------------------------------------------------
// Attention kernel: grid (s, h) = 1024 blocks, 256 threads, 2 blocks/SM.
// Warp owns 32 q rows (mt=2) and 32 kv rows. Projects Q/K/V for its head,
// runs attention, writes normalized O as fp16 A-frags to g_Of.
// Bias read as one LDG.128 per (kt, mt) from frag-major layout.
// ---------------------------------------------------------------------------
#define AWS_OFF 0
#define AKS_OFF 3072
#define AVS_OFF 7168
#define AMS_OFF 11264
#define ATTN_SMEM ((11264 + 256) * 4)
#define ONE2 0x3C003C00u

__global__ __launch_bounds__(256, 2) void attn_kernel(
    const float* __restrict__ mask) {
  extern __shared__ unsigned smu[];
  float* ms = (float*)(smu + AMS_OFF);

  const int tid = threadIdx.x;
  const int s = blockIdx.x, h = blockIdx.y;

  // stage this head's Wq/Wk/Wv frags (768 uint4)
  {
    uint4* dst = (uint4*)(smu + AWS_OFF);
#pragma unroll
    for (int i = tid; i < 768; i += 256) {
      int z = i >> 8, wi = i & 255;
      dst[i] = ((const uint4*)g_Wfu)[(z * 8 + h) * 256 + wi];
    }
  }
  ms[tid] = ((mask[s * 256 + tid] - 1.0f) * INF9 - 4.0f) * LOG2E;
  __syncthreads();

  const int w = tid >> 5, lane = tid & 31;
  const int r4 = lane >> 2, c4 = lane & 3;
  const int rtB = s * 16 + w * 2;  // this warp's abs row-tiles (q and kv)

  const uint2* Ws2 = (const uint2*)(smu + AWS_OFF);
  const uint2* Ks2 = (const uint2*)(smu + AKS_OFF);
  const uint2* Vs2 = (const uint2*)(smu + AVS_OFF);
  const uint4* Xqf4 = (const uint4*)g_Xqf;
  const uint4* Xkf4 = (const uint4*)g_Xkf;

  // ---- Q = Xq @ Wq_h -> qa A-frags ----
  uint4 qa[2][2];
  {
    float4 acc[2][4];
#pragma unroll
    for (int i = 0; i < 2; i++)
#pragma unroll
      for (int j = 0; j < 4; j++) acc[i][j] = make_float4(0.f, 0.f, 0.f, 0.f);
#pragma unroll
    for (int kg = 0; kg < 4; kg++) {
      uint4 A0 = Xqf4[((rtB + 0) * 4 + kg) * 32 + lane];
      uint4 A1 = Xqf4[((rtB + 1) * 4 + kg) * 32 + lane];
#pragma unroll
      for (int nf = 0; nf < 4; nf++) {
        uint2 B = Ws2[(kg * 4 + nf) * 32 + lane];
        mma16(acc[0][nf], A0.x, A0.y, A0.z, A0.w, B.x, B.y);
        mma16(acc[1][nf], A1.x, A1.y, A1.z, A1.w, B.x, B.y);
      }
    }
#pragma unroll
    for (int mt = 0; mt < 2; mt++)
#pragma unroll
      for (int kg = 0; kg < 2; kg++)
        qa[mt][kg] = make_uint4(pk(acc[mt][2 * kg].x, acc[mt][2 * kg].y),
                                pk(acc[mt][2 * kg].z, acc[mt][2 * kg].w),
                                pk(acc[mt][2 * kg + 1].x, acc[mt][2 * kg + 1].y),
                                pk(acc[mt][2 * kg + 1].z, acc[mt][2 * kg + 1].w));
  }

  // ---- K = Xkv @ Wk_h -> Ks scatter ----
  {
    float4 acc[2][4];
#pragma unroll
    for (int i = 0; i < 2; i++)
#pragma unroll
      for (int j = 0; j < 4; j++) acc[i][j] = make_float4(0.f, 0.f, 0.f, 0.f);
#pragma unroll
    for (int kg = 0; kg < 4; kg++) {
      uint4 A0 = Xkf4[((rtB + 0) * 4 + kg) * 32 + lane];
      uint4 A1 = Xkf4[((rtB + 1) * 4 + kg) * 32 + lane];
#pragma unroll
      for (int nf = 0; nf < 4; nf++) {
        uint2 B = Ws2[512 + (kg * 4 + nf) * 32 + lane];
        mma16(acc[0][nf], A0.x, A0.y, A0.z, A0.w, B.x, B.y);
        mma16(acc[1][nf], A1.x, A1.y, A1.z, A1.w, B.x, B.y);
      }
    }
#pragma unroll
    for (int mt = 0; mt < 2; mt++) {
      int kt = w * 2 + mt;  // local kv tile
#pragma unroll
      for (int nf = 0; nf < 4; nf++) {
        int kgd = nf >> 1, pp = nf & 1;
        smu[AKS_OFF + (((kt * 2 + kgd) * 2 + 0) * 32 + lane) * 2 + pp] =
            pk(acc[mt][nf].x, acc[mt][nf].y);
        smu[AKS_OFF + (((kt * 2 + kgd) * 2 + 1) * 32 + lane) * 2 + pp] =
            pk(acc[mt][nf].z, acc[mt][nf].w);
      }
    }
  }

  // ---- V = Xkv @ Wv_h -> Vs scatter ----
  {
    float4 acc[2][4];
#pragma unroll
    for (int i = 0; i < 2; i++)
#pragma unroll
      for (int j = 0; j < 4; j++) acc[i][j] = make_float4(0.f, 0.f, 0.f, 0.f);
#pragma unroll
    for (int kg = 0; kg < 4; kg++) {
      uint4 A0 = Xkf4[((rtB + 0) * 4 + kg) * 32 + lane];
      uint4 A1 = Xkf4[((rtB + 1) * 4 + kg) * 32 + lane];
#pragma unroll
      for (int nf = 0; nf < 4; nf++) {
        uint2 B = Ws2[1024 + (kg * 4 + nf) * 32 + lane];
        mma16(acc[0][nf], A0.x, A0.y, A0.z, A0.w, B.x, B.y);
        mma16(acc[1][nf], A1.x, A1.y, A1.z, A1.w, B.x, B.y);
      }
    }
    __half* Vh = (__half*)(smu + AVS_OFF);
    int e = r4 & 1, cp = r4 >> 1;
#pragma unroll
    for (int mt = 0; mt < 2; mt++) {
      int kt = w * 2 + mt;
#pragma unroll
      for (int nf = 0; nf < 4; nf++) {
        int b0 = (((kt * 4 + nf) * 32 + (2 * c4) * 4 + cp) * 4) + e;
        int b1 = b0 + 16;
        Vh[b0] = __float2half_rn(acc[mt][nf].x);
        Vh[b0 + 2] = __float2half_rn(acc[mt][nf].z);
        Vh[b1] = __float2half_rn(acc[mt][nf].y);
        Vh[b1 + 2] = __float2half_rn(acc[mt][nf].w);
      }
    }
  }
  __syncthreads();  // Ks/Vs ready

  // ---- attention ----
  float4 o[2][4];
#pragma unroll
  for (int mt = 0; mt < 2; mt++)
#pragma unroll
    for (int nf = 0; nf < 4; nf++) o[mt][nf] = make_float4(0.f, 0.f, 0.f, 0.f);
  float4 lpq[2] = {make_float4(0.f, 0.f, 0.f, 0.f),
                   make_float4(0.f, 0.f, 0.f, 0.f)};

  // frag-major bias: one uint4 per (kt, mt)
  const uint4* Bf4 = (const uint4*)g_B16;
  size_t bbase[2];
#pragma unroll
  for (int mt = 0; mt < 2; mt++)
    bbase[mt] = ((size_t)(h * 16 + w * 2 + mt) * 16) * 32 + lane;

  uint4 cbuf[2][2];  // [slot][mt]
#pragma unroll
  for (int sl = 0; sl < 2; sl++)
#pragma unroll
    for (int mt = 0; mt < 2; mt++) cbuf[sl][mt] = Bf4[bbase[mt] + sl * 32];

#pragma unroll 2
  for (int kt = 0; kt < 16; kt++) {
    const int kv0 = kt * 16;
    const int sl = kt & 1;

    float2 m0 = *(const float2*)(ms + kv0 + 2 * c4);
    float2 m1 = *(const float2*)(ms + kv0 + 8 + 2 * c4);

    float4 Sf[2][2];
#pragma unroll
    for (int mt = 0; mt < 2; mt++) {
      float2 c00 = h22f2(cbuf[sl][mt].x);  // nt0, row r4
      float2 c01 = h22f2(cbuf[sl][mt].y);  // nt0, row r4+8
      float2 c10 = h22f2(cbuf[sl][mt].z);  // nt1, row r4
      float2 c11 = h22f2(cbuf[sl][mt].w);  // nt1, row r4+8
      Sf[mt][0] = make_float4(c00.x + m0.x, c00.y + m0.y,
                              c01.x + m0.x, c01.y + m0.y);
      Sf[mt][1] = make_float4(c10.x + m1.x, c10.y + m1.y,
                              c11.x + m1.x, c11.y + m1.y);
    }

    if (kt < 14) {
#pragma unroll
      for (int mt = 0; mt < 2; mt++)
        cbuf[sl][mt] = Bf4[bbase[mt] + (kt + 2) * 32];
    }

#pragma unroll
    for (int kg = 0; kg < 2; kg++) {
      uint2 Kb0 = Ks2[((kt * 2 + kg) * 2 + 0) * 32 + lane];
      uint2 Kb1 = Ks2[((kt * 2 + kg) * 2 + 1) * 32 + lane];
#pragma unroll
      for (int mt = 0; mt < 2; mt++) {
        mma16(Sf[mt][0], qa[mt][kg].x, qa[mt][kg].y, qa[mt][kg].z,
              qa[mt][kg].w, Kb0.x, Kb0.y);
        mma16(Sf[mt][1], qa[mt][kg].x, qa[mt][kg].y, qa[mt][kg].z,
              qa[mt][kg].w, Kb1.x, Kb1.y);
      }
    }

    uint2 Vb[4];
#pragma unroll
    for (int nf = 0; nf < 4; nf++) Vb[nf] = Vs2[(kt * 4 + nf) * 32 + lane];

#pragma unroll
    for (int mt = 0; mt < 2; mt++) {
      float p00 = exp2f(Sf[mt][0].x), p01 = exp2f(Sf[mt][0].y);
      float p02 = exp2f(Sf[mt][0].z), p03 = exp2f(Sf[mt][0].w);
      float p10 = exp2f(Sf[mt][1].x), p11 = exp2f(Sf[mt][1].y);
      float p12 = exp2f(Sf[mt][1].z), p13 = exp2f(Sf[mt][1].w);
      unsigned pa0 = pk(p00, p01), pa1 = pk(p02, p03);
      unsigned pa2 = pk(p10, p11), pa3 = pk(p12, p13);
      mma16(lpq[mt], pa0, pa1, pa2, pa3, ONE2, ONE2);
#pragma unroll
      for (int nf = 0; nf < 4; nf++)
        mma16(o[mt][nf], pa0, pa1, pa2, pa3, Vb[nf].x, Vb[nf].y);
    }
  }

  // ---- normalize, pack to A-frags, write g_Of ----
  uint4* Of4 = (uint4*)g_Of;
#pragma unroll
  for (int mt = 0; mt < 2; mt++) {
    float inv0 = 1.0f / lpq[mt].x;
    float inv8 = 1.0f / lpq[mt].z;
    int rtA = rtB + mt;
#pragma unroll
    for (int kg = 0; kg < 2; kg++) {
      uint4 val = make_uint4(
          pk(o[mt][2 * kg].x * inv0, o[mt][2 * kg].y * inv0),
          pk(o[mt][2 * kg].z * inv8, o[mt][2 * kg].w * inv8),
          pk(o[mt][2 * kg + 1].x * inv0, o[mt][2 * kg + 1].y * inv0),
          pk(o[mt][2 * kg + 1].z * inv8, o[mt][2 * kg + 1].w * inv8));
      Of4[((size_t)rtA * 16 + h * 2 + kg) * 32 + lane] = val;
    }
  }
}

// ---------------------------------------------------------------------------
// Output projection: g_Of (fp16 A-frags) @ Wo + bo. Grid 256, 128 threads
// (4 warps x mt=2 = 8 row-tiles), 4 blocks/SM. Wo frags = 32 KB SMEM.
// ---------------------------------------------------------------------------
#define OPROJ_SMEM (8192 * 4)

__global__ __launch_bounds__(128, 4) void oproj_kernel(
    const float* __restrict__ bo, float* __restrict__ outg) {
  extern __shared__ unsigned smo[];

  const int tid = threadIdx.x;
  {
    uint4* dst = (uint4*)smo;
#pragma unroll
    for (int i = tid; i < 2048; i += 128)
      dst[i] = ((const uint4*)g_Wofu)[i];
  }
  __syncthreads();

  const int w = tid >> 5, lane = tid & 31;
  const int r4 = lane >> 2, c4 = lane & 3;
  const int rt0 = blockIdx.x * 8 + w * 2;

  const uint2* Wo2 = (const uint2*)smo;
  const uint4* Of4 = (const uint4*)g_Of;

  float4 acc[2][8];
#pragma unroll
  for (int i = 0; i < 2; i++)
#pragma unroll
    for (int j = 0; j < 8; j++) acc[i][j] = make_float4(0.f, 0.f, 0.f, 0.f);

#pragma unroll 4
  for (int kg = 0; kg < 16; kg++) {
    uint4 A0 = Of4[((size_t)(rt0 + 0) * 16 + kg) * 32 + lane];
    uint4 A1 = Of4[((size_t)(rt0 + 1) * 16 + kg) * 32 + lane];
#pragma unroll
    for (int nf = 0; nf < 8; nf++) {
      uint2 B = Wo2[(kg * 8 + nf) * 32 + lane];
      mma16(acc[0][nf], A0.x, A0.y, A0.z, A0.w, B.x, B.y);
      mma16(acc[1][nf], A1.x, A1.y, A1.z, A1.w, B.x, B.y);
    }
  }

#pragma unroll
  for (int mt = 0; mt < 2; mt++) {
    int row = (rt0 + mt) * 16 + r4;
#pragma unroll
    for (int nf = 0; nf < 8; nf++) {
      int col = nf * 8 + 2 * c4;
      float2 bb = *(const float2*)(bo + col);
      *(float2*)(outg + (size_t)row * 64 + col) =
          make_float2(acc[mt][nf].x + bb.x, acc[mt][nf].y + bb.y);
      *(float2*)(outg + (size_t)(row + 8) * 64 + col) =
          make_float2(acc[mt][nf].z + bb.x, acc[mt][nf].w + bb.y);
    }
  }
}

// ---------------------------------------------------------------------------
extern "C" void kernel_launch(void* const* d_in, const int* in_sizes, int n_in,
                              void* d_out, int out_size) {
  const float* input_q  = (const float*)d_in[0];
  const float* input_kv = (const float*)d_in[1];
  const float* mask     = (const float*)d_in[2];
  const float* bias     = (const float*)d_in[3];
  const float* wq       = (const float*)d_in[4];
  const float* wk       = (const float*)d_in[5];
  const float* wv       = (const float*)d_in[6];
  const float* wo       = (const float*)d_in[7];
  const float* bo       = (const float*)d_in[8];
  float* out = (float*)d_out;

  cudaFuncSetAttribute(attn_kernel, cudaFuncAttributeMaxDynamicSharedMemorySize,
                       ATTN_SMEM);
  cudaFuncSetAttribute(oproj_kernel, cudaFuncAttributeMaxDynamicSharedMemorySize,
                       OPROJ_SMEM);

  prep_kernel<<<1152, 256>>>(wq, wk, wv, wo, bias);
  stagex_kernel<<<2048, 256>>>(input_q, input_kv);
  attn_kernel<<<dim3(S_LEN, NH), 256, ATTN_SMEM>>>(mask);
  oproj_kernel<<<256, 128, OPROJ_SMEM>>>(bo, out);
}